// round 17
// baseline (speedup 1.0000x reference)
#include <cuda_runtime.h>
#include <cuda_bf16.h>
#include <cstdint>
#include <math.h>

#define MAXN  50000
#define MAXNP 50048
#define FDIM 128
#define TILE 128
#define NTH  256
#define PLANE  ((size_t)MAXN * FDIM)
#define PLANEP ((size_t)MAXNP * FDIM)

// XOR-swizzled layout (256B rows), 96 KB, 2 CTA/SM for all gemm kernels
#define SAH 0u
#define SAL 32768u
#define SBH 65536u
#define SBL 81920u
#define SMSZH 98304

// -------- scratch (aliased: g_bfA = mu planes then mv planes; g_M1 = M1 then vproj planar) --------
__device__ float g_M0[MAXN * FDIM];
__device__ float g_M1[3][MAXN * FDIM];
__device__ float g_M2[3][MAXN * FDIM];
__device__ float g_M3[3][MAXN * FDIM];
__device__ __nv_bfloat16 g_bfA[3][2][PLANEP];    // phase A: mu hi/lo; phase B: mv hi/lo
__device__ __nv_bfloat16 g_tmp[2][PLANEP];       // dense stage-1 out, pre-split
__device__ __nv_bfloat16 g_msS[2][PLANEP];       // ms, pre-split
__device__ __nv_bfloat16 g_Wimg[8][32768];       // [hi 16384 | lo 16384], [out][in]

// ================= helpers =================
__device__ __forceinline__ uint32_t smem_u32(const void* p) {
    uint32_t a;
    asm("{ .reg .u64 t; cvta.to.shared.u64 t, %1; cvt.u32.u64 %0, t; }" : "=r"(a) : "l"(p));
    return a;
}
__device__ __forceinline__ uint32_t swz(uint32_t r, uint32_t q) {
    return (r << 8) + ((q ^ (r & 7u)) << 4);
}
__device__ __forceinline__ void cpa16(uint32_t dst, const void* src) {
    asm volatile("cp.async.cg.shared.global [%0], [%1], 16;" :: "r"(dst), "l"(src));
}
__device__ __forceinline__ void cpa_commit() { asm volatile("cp.async.commit_group;"); }
template <int K> __device__ __forceinline__ void cpa_wait() {
    asm volatile("cp.async.wait_group %0;" :: "n"(K));
}
__device__ __forceinline__ void ldm4(uint32_t* r, uint32_t addr) {
    asm volatile("ldmatrix.sync.aligned.m8n8.x4.shared.b16 {%0,%1,%2,%3}, [%4];"
                 : "=r"(r[0]), "=r"(r[1]), "=r"(r[2]), "=r"(r[3]) : "r"(addr));
}
__device__ __forceinline__ void mma16816(float* c, const uint32_t* a, uint32_t b0, uint32_t b1) {
    asm volatile(
        "mma.sync.aligned.m16n8k16.row.col.f32.bf16.bf16.f32 "
        "{%0,%1,%2,%3}, {%4,%5,%6,%7}, {%8,%9}, {%0,%1,%2,%3};"
        : "+f"(c[0]), "+f"(c[1]), "+f"(c[2]), "+f"(c[3])
        : "r"(a[0]), "r"(a[1]), "r"(a[2]), "r"(a[3]), "r"(b0), "r"(b1));
}
__device__ __forceinline__ void split1(float x, unsigned short& h, unsigned short& l) {
    __nv_bfloat16 hb = __float2bfloat16(x);
    float r = x - __bfloat162float(hb);
    __nv_bfloat16 lb = __float2bfloat16(r);
    h = *(unsigned short*)&hb;
    l = *(unsigned short*)&lb;
}
__device__ __forceinline__ uint32_t pack2(unsigned short a, unsigned short b) {
    return (uint32_t)a | ((uint32_t)b << 16);
}
__device__ __forceinline__ float sigf(float x) { return 1.f / (1.f + __expf(-x)); }

// async copy of one HALF weight image (64 out-rows, hi+lo) into swizzled B planes
__device__ __forceinline__ void prefetch_B_half(uint32_t sb, const __nv_bfloat16* __restrict__ img,
                                                int h0) {
    for (int i = threadIdx.x; i < 2048; i += NTH) {
        int half = i >> 10, idx = i & 1023;
        uint32_t r = (uint32_t)(idx >> 4), q = (uint32_t)(idx & 15);
        const uint4* src = (const uint4*)(img + half * 16384 + (size_t)(h0 + r) * 128) + q;
        uint32_t dst = sb + (half ? SBL : SBH) + swz(r, q);
        cpa16(dst, src);
    }
    cpa_commit();
}
// async copy of a pre-split A tile (hi+lo planes) into swizzled A planes
__device__ __forceinline__ void prefetch_A_sp(uint32_t sb, const __nv_bfloat16* __restrict__ hi,
                                              const __nv_bfloat16* __restrict__ lo, int n0) {
    for (int i = threadIdx.x; i < TILE * 16; i += NTH) {
        uint32_t r = (uint32_t)(i >> 4), q = (uint32_t)(i & 15);
        uint32_t off = swz(r, q);
        cpa16(sb + SAH + off, (const uint4*)(hi + (size_t)(n0 + r) * FDIM) + q);
        cpa16(sb + SAL + off, (const uint4*)(lo + (size_t)(n0 + r) * FDIM) + q);
    }
    cpa_commit();
}
// load fp32 [128][128] from gmem (guarded), split into swizzled A planes
__device__ __forceinline__ void load_split_A_swz(char* sm, const float* __restrict__ src,
                                                 int n0, int N) {
    for (int i = threadIdx.x; i < TILE * 16; i += NTH) {
        uint32_t r = (uint32_t)(i >> 4), q = (uint32_t)(i & 15);
        float4 v0 = make_float4(0.f, 0.f, 0.f, 0.f), v1 = v0;
        if (n0 + (int)r < N) {
            const float* p = src + (size_t)(n0 + r) * FDIM + q * 8;
            v0 = *(const float4*)p;
            v1 = *(const float4*)(p + 4);
        }
        unsigned short h[8], l[8];
        split1(v0.x, h[0], l[0]); split1(v0.y, h[1], l[1]);
        split1(v0.z, h[2], l[2]); split1(v0.w, h[3], l[3]);
        split1(v1.x, h[4], l[4]); split1(v1.y, h[5], l[5]);
        split1(v1.z, h[6], l[6]); split1(v1.w, h[7], l[7]);
        uint32_t off = swz(r, q);
        *(uint4*)(sm + SAH + off) = make_uint4(pack2(h[0], h[1]), pack2(h[2], h[3]),
                                               pack2(h[4], h[5]), pack2(h[6], h[7]));
        *(uint4*)(sm + SAL + off) = make_uint4(pack2(l[0], l[1]), pack2(l[2], l[3]),
                                               pack2(l[4], l[5]), pack2(l[6], l[7]));
    }
}

// ---- 3-term split GEMM, N=64 half: 8 warps, grid 4(M)x2(N), warp tile 32x32 ----
__device__ __forceinline__ void gemm3_half(uint32_t sb, int warpM, int warpN, int lane,
                                           float acc[2][4][4]) {
    uint32_t arow = (uint32_t)(warpM * 32 + (lane & 15));
    uint32_t brow = (uint32_t)(warpN * 32 + (lane & 15));
    uint32_t qb = (uint32_t)(lane >> 4);
#pragma unroll
    for (int kc = 0; kc < 8; ++kc) {
        uint32_t q = (uint32_t)(kc * 2) + qb;
        uint32_t ah[2][4], al[2][4], bh[2][4], bl[2][4];
#pragma unroll
        for (int mt = 0; mt < 2; ++mt) {
            uint32_t off = swz(arow + (uint32_t)(mt * 16), q);
            ldm4(ah[mt], sb + SAH + off);
            ldm4(al[mt], sb + SAL + off);
        }
#pragma unroll
        for (int nt = 0; nt < 2; ++nt) {
            uint32_t off = swz(brow + (uint32_t)(nt * 16), q);
            ldm4(bh[nt], sb + SBH + off);
            ldm4(bl[nt], sb + SBL + off);
        }
#pragma unroll
        for (int mt = 0; mt < 2; ++mt)
#pragma unroll
            for (int nt = 0; nt < 2; ++nt) {
                mma16816(acc[mt][nt * 2 + 0], ah[mt], bh[nt][0], bh[nt][2]);
                mma16816(acc[mt][nt * 2 + 1], ah[mt], bh[nt][1], bh[nt][3]);
                mma16816(acc[mt][nt * 2 + 0], ah[mt], bl[nt][0], bl[nt][2]);
                mma16816(acc[mt][nt * 2 + 1], ah[mt], bl[nt][1], bl[nt][3]);
                mma16816(acc[mt][nt * 2 + 0], al[mt], bh[nt][0], bh[nt][2]);
                mma16816(acc[mt][nt * 2 + 1], al[mt], bh[nt][1], bh[nt][3]);
            }
    }
}
__device__ __forceinline__ void zero_acc_h(float acc[2][4][4]) {
#pragma unroll
    for (int m = 0; m < 2; ++m)
#pragma unroll
        for (int n = 0; n < 4; ++n)
#pragma unroll
            for (int j = 0; j < 4; ++j) acc[m][n][j] = 0.f;
}

// ================= device bodies =================
__device__ void dense1_feat_body(char* sm, int b, const float* __restrict__ in,
                                 const __nv_bfloat16* __restrict__ img,
                                 const float* __restrict__ bias, int N) {
    int tid = threadIdx.x, wid = tid >> 5, lane = tid & 31;
    int warpM = wid >> 1, warpN = wid & 1;
    int half = b & 1;
    int n0 = (b >> 1) * TILE;
    int h0 = half * 64;
    uint32_t sb = smem_u32(sm);
    int r0 = warpM * 32 + (lane >> 2);
    int c0b = h0 + warpN * 32 + (lane & 3) * 2;

    prefetch_B_half(sb, img, h0);
    load_split_A_swz(sm, in, n0, N);
    cpa_wait<0>();
    __syncthreads();

    float acc[2][4][4];
    zero_acc_h(acc);
    gemm3_half(sb, warpM, warpN, lane, acc);

#pragma unroll
    for (int mt = 0; mt < 2; ++mt)
#pragma unroll
        for (int hrow = 0; hrow < 2; ++hrow) {
            int n = n0 + r0 + mt * 16 + hrow * 8;
            if (n < N) {
#pragma unroll
                for (int nidx = 0; nidx < 4; ++nidx) {
                    int c = c0b + nidx * 8;
                    float2 bb = *(const float2*)(bias + c);
                    float x = acc[mt][nidx][hrow * 2 + 0] + bb.x;
                    float y = acc[mt][nidx][hrow * 2 + 1] + bb.y;
                    x *= sigf(x); y *= sigf(y);
                    unsigned short hx, lx, hy, ly;
                    split1(x, hx, lx); split1(y, hy, ly);
                    *(uint32_t*)((unsigned short*)g_tmp[0] + (size_t)n * FDIM + c) = pack2(hx, hy);
                    *(uint32_t*)((unsigned short*)g_tmp[1] + (size_t)n * FDIM + c) = pack2(lx, ly);
                }
            }
        }
}

__device__ void dense1_sp_body(char* sm, int b,
                               const __nv_bfloat16* __restrict__ aH,
                               const __nv_bfloat16* __restrict__ aL,
                               const __nv_bfloat16* __restrict__ img,
                               const float* __restrict__ bias, int N) {
    int tid = threadIdx.x, wid = tid >> 5, lane = tid & 31;
    int warpM = wid >> 1, warpN = wid & 1;
    int half = b & 1;
    int n0 = (b >> 1) * TILE;
    int h0 = half * 64;
    uint32_t sb = smem_u32(sm);
    int r0 = warpM * 32 + (lane >> 2);
    int c0b = h0 + warpN * 32 + (lane & 3) * 2;

    prefetch_B_half(sb, img, h0);
    prefetch_A_sp(sb, aH, aL, n0);
    cpa_wait<0>();
    __syncthreads();

    float acc[2][4][4];
    zero_acc_h(acc);
    gemm3_half(sb, warpM, warpN, lane, acc);

#pragma unroll
    for (int mt = 0; mt < 2; ++mt)
#pragma unroll
        for (int hrow = 0; hrow < 2; ++hrow) {
            int n = n0 + r0 + mt * 16 + hrow * 8;
            if (n < N) {
#pragma unroll
                for (int nidx = 0; nidx < 4; ++nidx) {
                    int c = c0b + nidx * 8;
                    float2 bb = *(const float2*)(bias + c);
                    float x = acc[mt][nidx][hrow * 2 + 0] + bb.x;
                    float y = acc[mt][nidx][hrow * 2 + 1] + bb.y;
                    x *= sigf(x); y *= sigf(y);
                    unsigned short hx, lx, hy, ly;
                    split1(x, hx, lx); split1(y, hy, ly);
                    *(uint32_t*)((unsigned short*)g_tmp[0] + (size_t)n * FDIM + c) = pack2(hx, hy);
                    *(uint32_t*)((unsigned short*)g_tmp[1] + (size_t)n * FDIM + c) = pack2(lx, ly);
                }
            }
        }
}

__device__ void dense2b_body(char* sm, int b,
                             const __nv_bfloat16* __restrict__ aH,
                             const __nv_bfloat16* __restrict__ aL,
                             const __nv_bfloat16* __restrict__ img,
                             const float* __restrict__ bias,
                             float* __restrict__ out, int N) {
    int tid = threadIdx.x, wid = tid >> 5, lane = tid & 31;
    int warpM = wid >> 1, warpN = wid & 1;
    int half = b & 1;
    int n0 = (b >> 1) * TILE;
    int h0 = half * 64;
    uint32_t sb = smem_u32(sm);
    int r0 = warpM * 32 + (lane >> 2);
    int c0b = h0 + warpN * 32 + (lane & 3) * 2;

    prefetch_B_half(sb, img, h0);
    prefetch_A_sp(sb, aH, aL, n0);
    cpa_wait<0>();
    __syncthreads();

    float acc[2][4][4];
    zero_acc_h(acc);
    gemm3_half(sb, warpM, warpN, lane, acc);

#pragma unroll
    for (int mt = 0; mt < 2; ++mt)
#pragma unroll
        for (int hrow = 0; hrow < 2; ++hrow) {
            int n = n0 + r0 + mt * 16 + hrow * 8;
            if (n < N) {
#pragma unroll
                for (int nidx = 0; nidx < 4; ++nidx) {
                    int c = c0b + nidx * 8;
                    float2 bb = *(const float2*)(bias + c);
                    *(float2*)(out + (size_t)n * FDIM + c) = make_float2(
                        acc[mt][nidx][hrow * 2 + 0] + bb.x,
                        acc[mt][nidx][hrow * 2 + 1] + bb.y);
                }
            }
        }
}

__device__ void muproj_body(char* sm, int b,
                            const __nv_bfloat16* __restrict__ imgT1,
                            const __nv_bfloat16* __restrict__ imgT2,
                            const __nv_bfloat16* __restrict__ imgT3,
                            float* __restrict__ M1, float* __restrict__ M2,
                            float* __restrict__ M3, int N) {
    int tid = threadIdx.x, wid = tid >> 5, lane = tid & 31;
    int warpM = wid >> 1, warpN = wid & 1;
    int half = b & 1;
    int n0 = (b >> 1) * TILE;
    int h0 = half * 64;
    uint32_t sb = smem_u32(sm);
    int r0 = warpM * 32 + (lane >> 2);
    int c0b = h0 + warpN * 32 + (lane & 3) * 2;

    const __nv_bfloat16* imgs[3] = {imgT1, imgT2, imgT3};
    float* Ms[3] = {M1, M2, M3};

    prefetch_B_half(sb, imgs[0], h0);
    prefetch_A_sp(sb, g_bfA[0][0], g_bfA[0][1], n0);
    for (int c = 0; c < 3; ++c) {
        for (int w = 0; w < 3; ++w) {
            cpa_wait<0>();
            __syncthreads();
            float acc[2][4][4];
            zero_acc_h(acc);
            gemm3_half(sb, warpM, warpN, lane, acc);
            __syncthreads();      // all smem reads done -> safe to overwrite
            if (w < 2) {
                prefetch_B_half(sb, imgs[w + 1], h0);
            } else if (c < 2) {
                prefetch_B_half(sb, imgs[0], h0);
                prefetch_A_sp(sb, g_bfA[c + 1][0], g_bfA[c + 1][1], n0);
            }
            float* dst = Ms[w] + (size_t)c * PLANE;
#pragma unroll
            for (int mt = 0; mt < 2; ++mt)
#pragma unroll
                for (int hrow = 0; hrow < 2; ++hrow) {
                    int n = n0 + r0 + mt * 16 + hrow * 8;
                    if (n < N) {
#pragma unroll
                        for (int nidx = 0; nidx < 4; ++nidx) {
                            int cc = c0b + nidx * 8;
                            *(float2*)(dst + (size_t)n * FDIM + cc) = make_float2(
                                acc[mt][nidx][hrow * 2 + 0], acc[mt][nidx][hrow * 2 + 1]);
                        }
                    }
                }
        }
    }
}

// vproj: pre-split A (g_bfA = mv planes), PLANAR output (contiguous stores)
__device__ void vproj_body(char* sm, int b, const __nv_bfloat16* __restrict__ imgV,
                           float* __restrict__ planar, int N) {
    int tid = threadIdx.x, wid = tid >> 5, lane = tid & 31;
    int warpM = wid >> 1, warpN = wid & 1;
    int half = b & 1;
    int n0 = (b >> 1) * TILE;
    int h0 = half * 64;
    uint32_t sb = smem_u32(sm);
    int r0 = warpM * 32 + (lane >> 2);
    int c0b = h0 + warpN * 32 + (lane & 3) * 2;

    prefetch_B_half(sb, imgV, h0);
    prefetch_A_sp(sb, g_bfA[0][0], g_bfA[0][1], n0);
#pragma unroll 1
    for (int c = 0; c < 3; ++c) {
        cpa_wait<0>();
        __syncthreads();
        float acc[2][4][4];
        zero_acc_h(acc);
        gemm3_half(sb, warpM, warpN, lane, acc);
        __syncthreads();
        if (c < 2) prefetch_A_sp(sb, g_bfA[c + 1][0], g_bfA[c + 1][1], n0);
        float* dst = planar + (size_t)c * PLANE;
#pragma unroll
        for (int mt = 0; mt < 2; ++mt)
#pragma unroll
            for (int hrow = 0; hrow < 2; ++hrow) {
                int n = n0 + r0 + mt * 16 + hrow * 8;
                if (n < N) {
#pragma unroll
                    for (int nidx = 0; nidx < 4; ++nidx) {
                        int a = c0b + nidx * 8;
                        *(float2*)(dst + (size_t)n * FDIM + a) = make_float2(
                            acc[mt][nidx][hrow * 2 + 0], acc[mt][nidx][hrow * 2 + 1]);
                    }
                }
            }
    }
}

// mu de-interleave+split (grid-stride over nblocks*NTH lanes)
__device__ void mu_split_body(const float* __restrict__ mu, int bid, int nblk, int N) {
    size_t total = (size_t)N * FDIM * 3;
    size_t stride = (size_t)nblk * NTH;
    for (size_t i = (size_t)bid * NTH + threadIdx.x; i < total; i += stride) {
        float v = __ldg(mu + i);
        int c = (int)(i % 3);
        size_t nf = i / 3;
        unsigned short h, l;
        split1(v, h, l);
        g_bfA[c][0][nf] = *(__nv_bfloat16*)&h;
        g_bfA[c][1][nf] = *(__nv_bfloat16*)&l;
    }
}

// planar -> interleaved [N, A, 3] (coalesced both sides)
__device__ void interleave_body(const float* __restrict__ planar, float* __restrict__ out,
                                int bid, int nblk, int N) {
    size_t total = (size_t)N * FDIM;
    size_t stride = (size_t)nblk * NTH;
    for (size_t i = (size_t)bid * NTH + threadIdx.x; i < total; i += stride) {
        float v0 = __ldg(planar + i);
        float v1 = __ldg(planar + PLANE + i);
        float v2 = __ldg(planar + 2 * PLANE + i);
        float* o = out + i * 3;
        o[0] = v0; o[1] = v1; o[2] = v2;
    }
}

// ================= fused kernels =================
__global__ void __launch_bounds__(NTH, 2) fuse1_kernel(          // dense1_feat | mu_split
    const float* __restrict__ feat, const float* __restrict__ mu,
    const __nv_bfloat16* __restrict__ imgQ1, const float* __restrict__ bq1,
    int nbG, int nblkMu, int N) {
    extern __shared__ char sm[];
    int b = blockIdx.x;
    if (b < nbG) dense1_feat_body(sm, b, feat, imgQ1, bq1, N);
    else         mu_split_body(mu, b - nbG, nblkMu, N);
}
__global__ void __launch_bounds__(NTH, 2) fuse2_kernel(          // dense2b(q) | muproj
    const __nv_bfloat16* __restrict__ imgQ2, const float* __restrict__ bq2,
    const __nv_bfloat16* __restrict__ imgT1, const __nv_bfloat16* __restrict__ imgT2,
    const __nv_bfloat16* __restrict__ imgT3,
    float* __restrict__ M0, float* __restrict__ M1, float* __restrict__ M2,
    float* __restrict__ M3, int nbG, int N) {
    extern __shared__ char sm[];
    int b = blockIdx.x;
    if (b < nbG) dense2b_body(sm, b, g_tmp[0], g_tmp[1], imgQ2, bq2, M0, N);
    else         muproj_body(sm, b - nbG, imgT1, imgT2, imgT3, M1, M2, M3, N);
}
__global__ void __launch_bounds__(NTH, 2) fuse3_kernel(          // dense1_sp(ms) | vproj
    const __nv_bfloat16* __restrict__ imgS1, const float* __restrict__ bs1,
    const __nv_bfloat16* __restrict__ imgV, float* __restrict__ planar,
    int nbG, int N) {
    extern __shared__ char sm[];
    int b = blockIdx.x;
    if (b < nbG) dense1_sp_body(sm, b, g_msS[0], g_msS[1], imgS1, bs1, N);
    else         vproj_body(sm, b - nbG, imgV, planar, N);
}
__global__ void __launch_bounds__(NTH, 2) fuse4_kernel(          // dense2b(s) | interleave
    const __nv_bfloat16* __restrict__ imgS2, const float* __restrict__ bs2,
    const float* __restrict__ planar,
    float* __restrict__ ms_out, float* __restrict__ mv_out,
    int nbG, int nblkIl, int N) {
    extern __shared__ char sm[];
    int b = blockIdx.x;
    if (b < nbG) dense2b_body(sm, b, g_tmp[0], g_tmp[1], imgS2, bs2, ms_out, N);
    else         interleave_body(planar, mv_out, b - nbG, nblkIl, N);
}

// ================= prep =================
struct WPtrs { const float* p[8]; };
__global__ void prep_weights(WPtrs wp) {
    int w = blockIdx.x;
    const float* src = wp.p[w];
    __nv_bfloat16* hi = g_Wimg[w];
    __nv_bfloat16* lo = g_Wimg[w] + 16384;
    for (int i = threadIdx.x; i < 16384; i += blockDim.x) {
        int k = i >> 7, g = i & 127;
        unsigned short h, l;
        split1(src[i], h, l);
        hi[g * 128 + k] = *(__nv_bfloat16*)&h;
        lo[g * 128 + k] = *(__nv_bfloat16*)&l;
    }
}

// ================= combine: writes pre-split ms (g_msS) + mv (g_bfA, reuse) =================
__global__ void __launch_bounds__(FDIM) combine_kernel(
    const float* __restrict__ T0, const float* __restrict__ T1,
    const float* __restrict__ T2, const float* __restrict__ T3,
    const float* __restrict__ M0, const float* __restrict__ M1,
    const float* __restrict__ M2, const float* __restrict__ M3, int N) {
    int n = blockIdx.x;
    __shared__ float st[40];
    int tid = threadIdx.x;
    if (tid == 0) st[0] = T0[n];
    if (tid < 3) st[1 + tid] = T1[(size_t)n * 3 + tid];
    if (tid >= 32 && tid < 41) st[4 + tid - 32] = T2[(size_t)n * 9 + (tid - 32)];
    if (tid >= 64 && tid < 91) st[13 + tid - 64] = T3[(size_t)n * 27 + (tid - 64)];
    __syncthreads();

    float t0 = st[0];
    float t1[3], t2[9], t3[27];
#pragma unroll
    for (int k = 0; k < 3; ++k) t1[k] = st[1 + k];
#pragma unroll
    for (int k = 0; k < 9; ++k) t2[k] = st[4 + k];
#pragma unroll
    for (int k = 0; k < 27; ++k) t3[k] = st[13 + k];

    size_t base = (size_t)n * FDIM + tid;
    float m0 = M0[base];
    float m1[3], m2[3], m3[3];
#pragma unroll
    for (int c = 0; c < 3; ++c) {
        m1[c] = M1[base + (size_t)c * PLANE];
        m2[c] = M2[base + (size_t)c * PLANE];
        m3[c] = M3[base + (size_t)c * PLANE];
    }

    float s = t0 * m0;
#pragma unroll
    for (int i = 0; i < 3; ++i) s += m1[i] * t1[i];
#pragma unroll
    for (int i = 0; i < 3; ++i)
#pragma unroll
        for (int j = 0; j < 3; ++j) s += m2[i] * m2[j] * t2[i * 3 + j];
#pragma unroll
    for (int i = 0; i < 3; ++i) {
        float mi = m3[i];
#pragma unroll
        for (int j = 0; j < 3; ++j) {
            float mij = mi * m3[j];
#pragma unroll
            for (int k = 0; k < 3; ++k) s += mij * m3[k] * t3[i * 9 + j * 3 + k];
        }
    }
    {
        unsigned short h, l;
        split1(s, h, l);
        g_msS[0][base] = *(__nv_bfloat16*)&h;
        g_msS[1][base] = *(__nv_bfloat16*)&l;
    }

#pragma unroll
    for (int i = 0; i < 3; ++i) {
        float v = t1[i] * m0;
#pragma unroll
        for (int j = 0; j < 3; ++j) v += t2[i * 3 + j] * m1[j];
#pragma unroll
        for (int j = 0; j < 3; ++j)
#pragma unroll
            for (int k = 0; k < 3; ++k) v += t3[i * 9 + j * 3 + k] * m2[j] * m2[k];
        unsigned short h, l;
        split1(v, h, l);
        g_bfA[i][0][base] = *(__nv_bfloat16*)&h;   // mu planes dead; reuse as mv
        g_bfA[i][1][base] = *(__nv_bfloat16*)&l;
    }
}

// ================= launch =================
extern "C" void kernel_launch(void* const* d_in, const int* in_sizes, int n_in,
                              void* d_out, int out_size) {
    const float* feat = (const float*)d_in[0];
    const float* mu   = (const float*)d_in[1];
    const float* T0   = (const float*)d_in[2];
    const float* T1   = (const float*)d_in[3];
    const float* T2   = (const float*)d_in[4];
    const float* T3   = (const float*)d_in[5];
    const float* Wq1  = (const float*)d_in[6];
    const float* bq1  = (const float*)d_in[7];
    const float* Wq2  = (const float*)d_in[8];
    const float* bq2  = (const float*)d_in[9];
    const float* WT1  = (const float*)d_in[10];
    const float* WT2  = (const float*)d_in[11];
    const float* WT3  = (const float*)d_in[12];
    const float* Ws1  = (const float*)d_in[13];
    const float* bs1  = (const float*)d_in[14];
    const float* Ws2  = (const float*)d_in[15];
    const float* bs2  = (const float*)d_in[16];
    const float* Wv   = (const float*)d_in[17];

    int N = in_sizes[0] / FDIM;
    if (N > MAXN) N = MAXN;

    float* out = (float*)d_out;
    float* ms_out = out;
    float* mv_out = out + (size_t)N * FDIM;

    cudaFuncSetAttribute(fuse1_kernel, cudaFuncAttributeMaxDynamicSharedMemorySize, SMSZH);
    cudaFuncSetAttribute(fuse2_kernel, cudaFuncAttributeMaxDynamicSharedMemorySize, SMSZH);
    cudaFuncSetAttribute(fuse3_kernel, cudaFuncAttributeMaxDynamicSharedMemorySize, SMSZH);
    cudaFuncSetAttribute(fuse4_kernel, cudaFuncAttributeMaxDynamicSharedMemorySize, SMSZH);

    float *pM0, *pM1, *pM2, *pM3;
    __nv_bfloat16* pW;
    cudaGetSymbolAddress((void**)&pM0, g_M0);
    cudaGetSymbolAddress((void**)&pM1, g_M1);
    cudaGetSymbolAddress((void**)&pM2, g_M2);
    cudaGetSymbolAddress((void**)&pM3, g_M3);
    cudaGetSymbolAddress((void**)&pW,  g_Wimg);

    WPtrs wp;
    wp.p[0] = Wq1; wp.p[1] = Wq2; wp.p[2] = WT1; wp.p[3] = WT2;
    wp.p[4] = WT3; wp.p[5] = Ws1; wp.p[6] = Ws2; wp.p[7] = Wv;
    prep_weights<<<8, 256>>>(wp);

    int nb = (N + TILE - 1) / TILE;
    int nbG = 2 * nb;            // gemm blocks per stage (row-tiles x col-halves)
    int nblkMu = 592;
    int nblkIl = 782;

    fuse1_kernel<<<nbG + nblkMu, NTH, SMSZH>>>(feat, mu, pW + 0 * 32768, bq1, nbG, nblkMu, N);
    fuse2_kernel<<<2 * nbG, NTH, SMSZH>>>(pW + 1 * 32768, bq2,
                                          pW + 2 * 32768, pW + 3 * 32768, pW + 4 * 32768,
                                          pM0, pM1, pM2, pM3, nbG, N);
    combine_kernel<<<N, FDIM>>>(T0, T1, T2, T3, pM0, pM1, pM2, pM3, N);
    fuse3_kernel<<<2 * nbG, NTH, SMSZH>>>(pW + 5 * 32768, bs1, pW + 7 * 32768, pM1, nbG, N);
    fuse4_kernel<<<nbG + nblkIl, NTH, SMSZH>>>(pW + 6 * 32768, bs2, pM1, ms_out, mv_out,
                                               nbG, nblkIl, N);
}